// round 1
// baseline (speedup 1.0000x reference)
#include <cuda_runtime.h>
#include <math.h>
#include <float.h>

// Problem constants (fixed by the dataset)
#define BSZ 2
#define SEQ 2048
#define NH  16
#define HD  64
#define BM  64          // query tile
#define BN  64          // key tile
#define NTHREADS 256
#define SM_SCALE 0.125f // 1/sqrt(64)

// Flash-attention with additive bias + causal + segment mask.
// Segment ids m are sorted per batch, so the valid key range for query qg is
// the contiguous [lower_bound(m, m[qg]), qg]. We binary-search once per block
// (and per row) and skip whole key tiles below the segment start.
//
// Thread layout: 256 threads as 16x16 (tx = tid&15, ty = tid>>4).
//   S tile (64x64): thread owns rows 4*ty+ii (ii<4), cols tx+16*jj (jj<4).
//   O tile (64x64): thread owns rows 4*ty+ii, cols {2tx,2tx+1,2tx+32,2tx+33}.
// K tile is XOR-swizzled on float2 granularity so stride-64 column reads are
// bank-conflict-free. P overlays the K smem region between the two GEMMs.

__global__ __launch_bounds__(NTHREADS, 2)
void flash_attn_kernel(const float* __restrict__ q,
                       const float* __restrict__ k,
                       const float* __restrict__ v,
                       const float* __restrict__ bias,
                       const int*   __restrict__ m,
                       float* __restrict__ out)
{
    __shared__ float Qs[BM * 64];
    __shared__ float Ks[BN * 64];   // swizzled K; reused as P after S phase
    __shared__ float Vs[BN * 64];

    const int tid = threadIdx.x;
    const int tx  = tid & 15;
    const int ty  = tid >> 4;
    const int qt  = blockIdx.x;     // query tile index
    const int h   = blockIdx.y;
    const int b   = blockIdx.z;
    const int q0  = qt * BM;

    const int* mb = m + b * SEQ;

    // Per-row segment starts (rows 4*ty+ii). m is sorted ascending, so
    // seg_start = lower_bound(mb, mb[qg]).
    int seg_start[4];
#pragma unroll
    for (int ii = 0; ii < 4; ii++) {
        int qg  = q0 + 4 * ty + ii;
        int tgt = mb[qg];
        int lo = 0, hi = qg;
        while (lo < hi) { int mid = (lo + hi) >> 1; if (mb[mid] < tgt) lo = mid + 1; else hi = mid; }
        seg_start[ii] = lo;
    }
    // Block-wide first key tile: based on row q0 (minimum segment in this tile).
    int kt0;
    {
        int tgt = mb[q0];
        int lo = 0, hi = q0;
        while (lo < hi) { int mid = (lo + hi) >> 1; if (mb[mid] < tgt) lo = mid + 1; else hi = mid; }
        kt0 = lo >> 6;
    }

    const long long row_stride = (long long)NH * HD;  // 1024 floats between tokens
    const float* qbase = q    + (((long long)b * SEQ + q0) * NH + h) * HD;
    const float* kbase = k    + (((long long)b * SEQ) * NH + h) * HD;
    const float* vbase = v    + (((long long)b * SEQ) * NH + h) * HD;
    const float* bbase = bias + (((long long)b * NH + h) * SEQ + q0) * SEQ;

    // Load Q tile (coalesced float4; plain layout — all GEMM reads are broadcast)
#pragma unroll
    for (int e = tid; e < BM * 16; e += NTHREADS) {
        int r = e >> 4, cg = e & 15;
        float4 val = *(const float4*)(qbase + (long long)r * row_stride + 4 * cg);
        *(float4*)&Qs[r * 64 + 4 * cg] = val;
    }

    float o[4][4];
    float mi[4], li[4];
#pragma unroll
    for (int ii = 0; ii < 4; ii++) {
        mi[ii] = -FLT_MAX; li[ii] = 0.f;
#pragma unroll
        for (int jj = 0; jj < 4; jj++) o[ii][jj] = 0.f;
    }

    for (int kt = kt0; kt <= qt; kt++) {
        const int k0 = kt * BN;
        __syncthreads();   // previous iteration's P/V reads done; smem free

        // Load K (XOR-swizzled float2 pairs) and V (plain) tiles
#pragma unroll
        for (int e = tid; e < BN * 16; e += NTHREADS) {
            int r = e >> 4, cg = e & 15;
            float4 kv4 = *(const float4*)(kbase + (long long)(k0 + r) * row_stride + 4 * cg);
            int c2 = 2 * cg;
            *(float2*)&Ks[r * 64 + 2 * ((c2)     ^ (r & 15))] = make_float2(kv4.x, kv4.y);
            *(float2*)&Ks[r * 64 + 2 * ((c2 + 1) ^ (r & 15))] = make_float2(kv4.z, kv4.w);
            float4 vv4 = *(const float4*)(vbase + (long long)(k0 + r) * row_stride + 4 * cg);
            *(float4*)&Vs[r * 64 + 4 * cg] = vv4;
        }
        __syncthreads();

        // ---- S = Q @ K^T (fp32, register 4x4 tile, float2 smem loads) ----
        float acc[4][4];
#pragma unroll
        for (int ii = 0; ii < 4; ii++)
#pragma unroll
            for (int jj = 0; jj < 4; jj++) acc[ii][jj] = 0.f;

#pragma unroll 8
        for (int c2 = 0; c2 < 32; c2++) {
            float2 qv[4], kv[4];
#pragma unroll
            for (int ii = 0; ii < 4; ii++)
                qv[ii] = *(const float2*)&Qs[(4 * ty + ii) * 64 + 2 * c2];
#pragma unroll
            for (int jj = 0; jj < 4; jj++) {
                int kj = tx + 16 * jj;
                kv[jj] = *(const float2*)&Ks[kj * 64 + 2 * (c2 ^ (kj & 15))];
            }
#pragma unroll
            for (int ii = 0; ii < 4; ii++)
#pragma unroll
                for (int jj = 0; jj < 4; jj++)
                    acc[ii][jj] += qv[ii].x * kv[jj].x + qv[ii].y * kv[jj].y;
        }

        // ---- mask + bias + online softmax (rows reduce over the 16 tx lanes) ----
        float p[4][4];
#pragma unroll
        for (int ii = 0; ii < 4; ii++) {
            const int qg = q0 + 4 * ty + ii;
            const float* brow = bbase + (long long)(4 * ty + ii) * SEQ + k0;
            float rmax = -FLT_MAX;
#pragma unroll
            for (int jj = 0; jj < 4; jj++) {
                int kg = k0 + tx + 16 * jj;
                bool valid = (kg <= qg) && (kg >= seg_start[ii]);
                float lg = -FLT_MAX;
                if (valid)  // predicated: masked bias elements are never fetched
                    lg = acc[ii][jj] * SM_SCALE + brow[tx + 16 * jj];
                p[ii][jj] = lg;
                rmax = fmaxf(rmax, lg);
            }
#pragma unroll
            for (int off = 8; off >= 1; off >>= 1)
                rmax = fmaxf(rmax, __shfl_xor_sync(0xffffffffu, rmax, off));
            float mnew  = fmaxf(mi[ii], rmax);
            float scl   = __expf(mi[ii] - mnew);   // both -FLT_MAX -> exp(0)=1, l==0 so harmless
            float rsum  = 0.f;
#pragma unroll
            for (int jj = 0; jj < 4; jj++) {
                float pv = (p[ii][jj] == -FLT_MAX) ? 0.f : __expf(p[ii][jj] - mnew);
                p[ii][jj] = pv;
                rsum += pv;
            }
#pragma unroll
            for (int off = 8; off >= 1; off >>= 1)
                rsum += __shfl_xor_sync(0xffffffffu, rsum, off);
            li[ii] = li[ii] * scl + rsum;
            mi[ii] = mnew;
#pragma unroll
            for (int jj = 0; jj < 4; jj++) o[ii][jj] *= scl;
        }

        __syncthreads();   // all threads done reading Ks
        // Write P into the Ks region (plain layout; PV reads are broadcast)
#pragma unroll
        for (int ii = 0; ii < 4; ii++)
#pragma unroll
            for (int jj = 0; jj < 4; jj++)
                Ks[(4 * ty + ii) * 64 + tx + 16 * jj] = p[ii][jj];
        __syncthreads();

        // ---- O += P @ V ----
#pragma unroll 8
        for (int kj = 0; kj < 64; kj++) {
            float pr[4];
#pragma unroll
            for (int ii = 0; ii < 4; ii++) pr[ii] = Ks[(4 * ty + ii) * 64 + kj];
            float2 v0 = *(const float2*)&Vs[kj * 64 + 2 * tx];
            float2 v1 = *(const float2*)&Vs[kj * 64 + 32 + 2 * tx];
#pragma unroll
            for (int ii = 0; ii < 4; ii++) {
                o[ii][0] += pr[ii] * v0.x;
                o[ii][1] += pr[ii] * v0.y;
                o[ii][2] += pr[ii] * v1.x;
                o[ii][3] += pr[ii] * v1.y;
            }
        }
    }

    // ---- epilogue: normalize and store (causal diagonal guarantees li > 0) ----
    float* obase = out + (((long long)b * SEQ + q0) * NH + h) * HD;
#pragma unroll
    for (int ii = 0; ii < 4; ii++) {
        float inv = 1.f / li[ii];
        float* orow = obase + (long long)(4 * ty + ii) * row_stride;
        *(float2*)&orow[2 * tx]      = make_float2(o[ii][0] * inv, o[ii][1] * inv);
        *(float2*)&orow[32 + 2 * tx] = make_float2(o[ii][2] * inv, o[ii][3] * inv);
    }
}

extern "C" void kernel_launch(void* const* d_in, const int* in_sizes, int n_in,
                              void* d_out, int out_size)
{
    const float* q    = (const float*)d_in[0];
    const float* k    = (const float*)d_in[1];
    const float* v    = (const float*)d_in[2];
    const float* bias = (const float*)d_in[3];
    const int*   m    = (const int*)d_in[4];
    float* out = (float*)d_out;

    dim3 grid(SEQ / BM, NH, BSZ);   // 32 x 16 x 2 = 1024 blocks
    flash_attn_kernel<<<grid, NTHREADS>>>(q, k, v, bias, m, out);
}